// round 2
// baseline (speedup 1.0000x reference)
#include <cuda_runtime.h>
#include <math.h>

#define DIMV 1024
#define LSEQ 2048
#define BATCH 8
#define MTOK (BATCH*LSEQ)   /* 16384 tokens */
#define ACTV 256
#define HIDV 256
#define KW 5
#define EPSV 1e-6f

// ---------------- scratch (device globals: allocation-guard safe) ----------------
__device__ float g_xn [(size_t)MTOK*DIMV];   // RMSNorm output
__device__ float g_xc [(size_t)MTOK*DIMV];   // depthwise conv output
__device__ float g_rec[(size_t)MTOK*ACTV];   // EMA scan output (first ACT channels)
__device__ float g_y  [(size_t)MTOK*DIMV];   // x_conv + x_rec
__device__ float g_g1 [(size_t)MTOK*DIMV];   // y@W1^T + b1
__device__ float g_g2 [(size_t)MTOK*DIMV];   // y@W2^T + b2
__device__ float g_y2 [(size_t)MTOK*DIMV];   // y + sig*tanh
__device__ float g_t  [(size_t)MTOK*HIDV];   // gelu(y2@down^T + db)

// ---------------- RMSNorm: one block per token ----------------
__global__ void rmsnorm_kernel(const float* __restrict__ x,
                               const float* __restrict__ norm_w)
{
    int m = blockIdx.x;
    const float4* xr = (const float4*)(x + (size_t)m * DIMV);
    float4 v = xr[threadIdx.x];                       // 256 thr * 4 = 1024
    float ss = v.x*v.x + v.y*v.y + v.z*v.z + v.w*v.w;
    #pragma unroll
    for (int o = 16; o; o >>= 1) ss += __shfl_xor_sync(0xffffffffu, ss, o);
    __shared__ float red[8];
    if ((threadIdx.x & 31) == 0) red[threadIdx.x >> 5] = ss;
    __syncthreads();
    float tot = red[0]+red[1]+red[2]+red[3]+red[4]+red[5]+red[6]+red[7];
    float inv = rsqrtf(tot * (1.0f / DIMV) + EPSV);
    float4 w4 = ((const float4*)norm_w)[threadIdx.x];
    float4 o4;
    o4.x = v.x * inv * w4.x;
    o4.y = v.y * inv * w4.y;
    o4.z = v.z * inv * w4.z;
    o4.w = v.w * inv * w4.w;
    ((float4*)(g_xn + (size_t)m * DIMV))[threadIdx.x] = o4;
}

// ---------------- EMA scan: one thread per (batch, channel<ACT) ----------------
__global__ void scan_kernel(const float* __restrict__ alpha,
                            const float* __restrict__ beta)
{
    int idx = blockIdx.x * blockDim.x + threadIdx.x;   // 0..2047
    int b = idx / ACTV, c = idx % ACTV;
    float a = alpha[c], be = beta[c], h = 0.0f;
    const float* xp = g_xn + (size_t)b * LSEQ * DIMV + c;
    float*       rp = g_rec + (size_t)b * LSEQ * ACTV + c;
    #pragma unroll 1
    for (int t = 0; t < LSEQ; t += 8) {
        float v0 = xp[(size_t)(t+0)*DIMV];
        float v1 = xp[(size_t)(t+1)*DIMV];
        float v2 = xp[(size_t)(t+2)*DIMV];
        float v3 = xp[(size_t)(t+3)*DIMV];
        float v4 = xp[(size_t)(t+4)*DIMV];
        float v5 = xp[(size_t)(t+5)*DIMV];
        float v6 = xp[(size_t)(t+6)*DIMV];
        float v7 = xp[(size_t)(t+7)*DIMV];
        h = a*h + be*v0; rp[(size_t)(t+0)*ACTV] = h;
        h = a*h + be*v1; rp[(size_t)(t+1)*ACTV] = h;
        h = a*h + be*v2; rp[(size_t)(t+2)*ACTV] = h;
        h = a*h + be*v3; rp[(size_t)(t+3)*ACTV] = h;
        h = a*h + be*v4; rp[(size_t)(t+4)*ACTV] = h;
        h = a*h + be*v5; rp[(size_t)(t+5)*ACTV] = h;
        h = a*h + be*v6; rp[(size_t)(t+6)*ACTV] = h;
        h = a*h + be*v7; rp[(size_t)(t+7)*ACTV] = h;
    }
}

// ---------------- depthwise conv K=5 along L, zero-padded per batch ----------------
__global__ void conv_kernel(const float* __restrict__ dw_w,
                            const float* __restrict__ dw_b)
{
    int idx = blockIdx.x * 256 + threadIdx.x;   // one thread -> (token, 4 channels)
    int m = idx >> 8;
    int d = (idx & 255) << 2;
    int b = m / LSEQ, l = m % LSEQ;
    float4 acc = *(const float4*)(dw_b + d);
    #pragma unroll
    for (int k = 0; k < KW; k++) {
        int ln = l + k - 2;
        if (ln >= 0 && ln < LSEQ) {
            float4 xv = *(const float4*)(g_xn + (size_t)(b*LSEQ + ln) * DIMV + d);
            acc.x += xv.x * __ldg(&dw_w[(d+0)*KW + k]);
            acc.y += xv.y * __ldg(&dw_w[(d+1)*KW + k]);
            acc.z += xv.z * __ldg(&dw_w[(d+2)*KW + k]);
            acc.w += xv.w * __ldg(&dw_w[(d+3)*KW + k]);
        }
    }
    *(float4*)(g_xc + (size_t)m * DIMV + d) = acc;
}

// ---------------- tiled SIMT GEMM: C[m,n] = epi( sum_k A[m,k]*W[n,k] + bias[n] ) ----
#define BM 128
#define BN 128
#define BKG 16

#define EPI_STORE 0   // C = acc + bias
#define EPI_PW    1   // C = acc + bias + (n<ACT ? rec[m,n] : xn[m,n])
#define EPI_GELU  2   // C = gelu(acc + bias)        (exact erf)
#define EPI_FINAL 3   // C = aux0[m,n] + acc + bias + aux1[m,n]   (y2 + up + residual)

template<int EPI>
__global__ __launch_bounds__(256, 2)
void gemm_kernel(const float* __restrict__ A, const float* __restrict__ W,
                 const float* __restrict__ bias, float* __restrict__ C,
                 int M, int N, int K,
                 const float* __restrict__ aux0, const float* __restrict__ aux1)
{
    __shared__ float As[BKG][BM + 4];
    __shared__ float Bs[BKG][BN + 4];

    const int tid = threadIdx.x;
    const int tx = tid & 15;          // n-direction (8 cols)
    const int ty = tid >> 4;          // m-direction (8 rows)
    const int bm = blockIdx.y * BM;
    const int bn = blockIdx.x * BN;

    float acc[8][8];
    #pragma unroll
    for (int i = 0; i < 8; i++)
        #pragma unroll
        for (int j = 0; j < 8; j++) acc[i][j] = 0.0f;

    for (int k0 = 0; k0 < K; k0 += BKG) {
        // stage A,B tiles (transposed into [k][row]) — 2 float4 each per thread
        #pragma unroll
        for (int q = 0; q < 2; q++) {
            int f  = tid + q * 256;          // 0..511
            int r  = f >> 2;                 // 0..127
            int c4 = (f & 3) << 2;           // 0,4,8,12
            float4 av = *(const float4*)(A + (size_t)(bm + r) * K + k0 + c4);
            As[c4+0][r] = av.x; As[c4+1][r] = av.y;
            As[c4+2][r] = av.z; As[c4+3][r] = av.w;
            float4 bv = *(const float4*)(W + (size_t)(bn + r) * K + k0 + c4);
            Bs[c4+0][r] = bv.x; Bs[c4+1][r] = bv.y;
            Bs[c4+2][r] = bv.z; Bs[c4+3][r] = bv.w;
        }
        __syncthreads();

        #pragma unroll
        for (int kk = 0; kk < BKG; kk++) {
            float a0[8], b0[8];
            *(float4*)&a0[0] = *(const float4*)&As[kk][ty*8];
            *(float4*)&a0[4] = *(const float4*)&As[kk][ty*8 + 4];
            *(float4*)&b0[0] = *(const float4*)&Bs[kk][tx*8];
            *(float4*)&b0[4] = *(const float4*)&Bs[kk][tx*8 + 4];
            #pragma unroll
            for (int i = 0; i < 8; i++)
                #pragma unroll
                for (int j = 0; j < 8; j++)
                    acc[i][j] += a0[i] * b0[j];
        }
        __syncthreads();
    }

    #pragma unroll
    for (int i = 0; i < 8; i++) {
        int m = bm + ty*8 + i;
        size_t rowC = (size_t)m * N;
        #pragma unroll
        for (int j = 0; j < 8; j++) {
            int n = bn + tx*8 + j;
            float v = acc[i][j] + bias[n];
            if (EPI == EPI_PW) {
                v += (n < ACTV) ? g_rec[(size_t)m*ACTV + n]
                                : g_xn [(size_t)m*DIMV + n];
            } else if (EPI == EPI_GELU) {
                v = 0.5f * v * (1.0f + erff(v * 0.70710678118654752f));
            } else if (EPI == EPI_FINAL) {
                v += aux0[rowC + n] + aux1[rowC + n];
            }
            C[rowC + n] = v;
        }
    }
}

// ---------------- gated elementwise: y2 = y + sigmoid(g1)*tanh(g2) ----------------
__global__ void glu_kernel()
{
    size_t i = (size_t)blockIdx.x * 256 + threadIdx.x;
    float4 yv = ((const float4*)g_y )[i];
    float4 av = ((const float4*)g_g1)[i];
    float4 bv = ((const float4*)g_g2)[i];
    float4 o;
    o.x = yv.x + (1.0f/(1.0f+expf(-av.x))) * tanhf(bv.x);
    o.y = yv.y + (1.0f/(1.0f+expf(-av.y))) * tanhf(bv.y);
    o.z = yv.z + (1.0f/(1.0f+expf(-av.z))) * tanhf(bv.z);
    o.w = yv.w + (1.0f/(1.0f+expf(-av.w))) * tanhf(bv.w);
    ((float4*)g_y2)[i] = o;
}

// ---------------- host launcher ----------------
extern "C" void kernel_launch(void* const* d_in, const int* in_sizes, int n_in,
                              void* d_out, int out_size)
{
    const float* x      = (const float*)d_in[0];
    const float* norm_w = (const float*)d_in[1];
    const float* dw_w   = (const float*)d_in[2];
    const float* dw_b   = (const float*)d_in[3];
    const float* pw_w   = (const float*)d_in[4];
    const float* pw_b   = (const float*)d_in[5];
    const float* alpha  = (const float*)d_in[6];
    const float* beta   = (const float*)d_in[7];
    const float* W1_w   = (const float*)d_in[8];
    const float* W1_b   = (const float*)d_in[9];
    const float* W2_w   = (const float*)d_in[10];
    const float* W2_b   = (const float*)d_in[11];
    const float* down_w = (const float*)d_in[12];
    const float* down_b = (const float*)d_in[13];
    const float* up_w   = (const float*)d_in[14];
    const float* up_b   = (const float*)d_in[15];
    float* out = (float*)d_out;

    float *p_xn, *p_xc, *p_y, *p_g1, *p_g2, *p_y2, *p_t;
    cudaGetSymbolAddress((void**)&p_xn, g_xn);
    cudaGetSymbolAddress((void**)&p_xc, g_xc);
    cudaGetSymbolAddress((void**)&p_y , g_y );
    cudaGetSymbolAddress((void**)&p_g1, g_g1);
    cudaGetSymbolAddress((void**)&p_g2, g_g2);
    cudaGetSymbolAddress((void**)&p_y2, g_y2);
    cudaGetSymbolAddress((void**)&p_t , g_t );

    // 1) RMSNorm
    rmsnorm_kernel<<<MTOK, 256>>>(x, norm_w);
    // 2) EMA scan (depends only on xn)
    scan_kernel<<<8, 256>>>(alpha, beta);
    // 3) depthwise conv
    conv_kernel<<<(MTOK * (DIMV/4)) / 256, 256>>>(dw_w, dw_b);
    // 4) pointwise GEMM, epilogue merges bias + rec/xn  -> y
    {
        dim3 g(DIMV/BN, MTOK/BM);
        gemm_kernel<EPI_PW><<<g, 256>>>(p_xc, pw_w, pw_b, p_y,
                                        MTOK, DIMV, DIMV, nullptr, nullptr);
    }
    // 5) gate GEMMs
    {
        dim3 g(DIMV/BN, MTOK/BM);
        gemm_kernel<EPI_STORE><<<g, 256>>>(p_y, W1_w, W1_b, p_g1,
                                           MTOK, DIMV, DIMV, nullptr, nullptr);
        gemm_kernel<EPI_STORE><<<g, 256>>>(p_y, W2_w, W2_b, p_g2,
                                           MTOK, DIMV, DIMV, nullptr, nullptr);
    }
    // 6) y2 = y + sigmoid(g1)*tanh(g2)
    glu_kernel<<<(MTOK * (DIMV/4)) / 256, 256>>>();
    // 7) down-proj + exact GELU -> t  [16384 x 256]
    {
        dim3 g(HIDV/BN, MTOK/BM);
        gemm_kernel<EPI_GELU><<<g, 256>>>(p_y2, down_w, down_b, p_t,
                                          MTOK, HIDV, DIMV, nullptr, nullptr);
    }
    // 8) up-proj + y2 + residual -> out
    {
        dim3 g(DIMV/BN, MTOK/BM);
        gemm_kernel<EPI_FINAL><<<g, 256>>>(p_t, up_w, up_b, out,
                                           MTOK, DIMV, HIDV, p_y2, x);
    }
}